// round 5
// baseline (speedup 1.0000x reference)
#include <cuda_runtime.h>
#include <cuda_bf16.h>

#define CKD 128
typedef unsigned long long ull;

// ---------------- static scratch ----------------
__device__ float  g_xs[(long)16*8191*128];
__device__ float  g_d [(long)16*4096*128];
__device__ float  g_ud[(long)16*8191*128];
__device__ float  g_us[(long)16*8191*128];
__device__ float2 g_part[(long)2*16*16*64*128];
__device__ float2 g_ftd[16*64*128];
__device__ float2 g_ftx[16*64*128];
__device__ float2 g_oud[16*64*128];
__device__ float2 g_ous[16*64*128];
__device__ float2 g_wt[(long)3*64*128*128];
__device__ float2 g_tw[4096+64];

// ---------------- f32x2 helpers ----------------
__device__ __forceinline__ ull pk2(float x, float y){
    ull r; asm("mov.b64 %0, {%1, %2};" : "=l"(r) : "f"(x), "f"(y)); return r;
}
__device__ __forceinline__ float2 up2(ull v){
    float2 r; asm("mov.b64 {%0, %1}, %2;" : "=f"(r.x), "=f"(r.y) : "l"(v)); return r;
}
__device__ __forceinline__ void ffma2(ull &acc, ull a, ull b){
    asm("fma.rn.f32x2 %0, %1, %2, %0;" : "+l"(acc) : "l"(a), "l"(b));
}

// ---------------- base twiddle table ----------------
__global__ void k_base(){
    int r = blockIdx.x*blockDim.x + threadIdx.x;
    if (r >= 4096) return;
    float s, c;
    sincospif(r/2048.0f, &s, &c);
    g_tw[r] = make_float2(c, -s);
    if (r < 64) g_tw[4096+r] = make_float2(0.f, 0.f);
}

// ---------------- weight transpose (i,o,m) -> (m,i,o), all 3 matrices ----------------
__global__ void k_wtrans(const float* __restrict__ Ar, const float* __restrict__ Ai,
                         const float* __restrict__ Br, const float* __restrict__ Bi,
                         const float* __restrict__ Cr, const float* __restrict__ Ci){
    long gidx = blockIdx.x*(long)blockDim.x + threadIdx.x;
    const long per = (long)64*128*128;
    if (gidx >= 3*per) return;
    int mat = (int)(gidx / per);
    long idx = gidx - (long)mat*per;
    const float* wr = mat==0 ? Ar : (mat==1 ? Br : Cr);
    const float* wi = mat==0 ? Ai : (mat==1 ? Bi : Ci);
    int m = (int)(idx & 63);
    int o = (int)((idx >> 6) & 127);
    int i = (int)(idx >> 13);
    g_wt[((long)mat*64 + m)*16384 + (long)i*128 + o] = make_float2(wr[idx], wi[idx]);
}

// ---------------- wavelet decompose ----------------
__global__ void __launch_bounds__(256) k_decompose(const float* __restrict__ xext, long xoff,
        long soff, const float* __restrict__ ecs, const float* __restrict__ ecd, int nh){
    __shared__ ull f[128];
    if (threadIdx.x < 128) f[threadIdx.x] = pk2(ecs[threadIdx.x], ecd[threadIdx.x]);
    __syncthreads();
    long idx = blockIdx.x*(long)blockDim.x + threadIdx.x;
    if (idx >= (long)16*nh*16) return;
    int c = (int)(idx & 15);
    long bt = idx >> 4;
    const float* xin = xext ? xext : (g_xs + xoff);
    const float* pe = xin + bt*2*CKD + c*8;
    float4 e0 = *(const float4*)(pe);
    float4 e1 = *(const float4*)(pe+4);
    float4 o0 = *(const float4*)(pe+CKD);
    float4 o1 = *(const float4*)(pe+CKD+4);
    float xa[16] = {e0.x,e0.y,e0.z,e0.w, e1.x,e1.y,e1.z,e1.w,
                    o0.x,o0.y,o0.z,o0.w, o1.x,o1.y,o1.z,o1.w};
    ull acc[8];
    #pragma unroll
    for (int ko=0;ko<8;++ko) acc[ko]=0ull;
    #pragma unroll
    for (int j=0;j<16;++j){
        ull vj = pk2(xa[j], xa[j]);
        #pragma unroll
        for (int ko=0;ko<8;++ko) ffma2(acc[ko], vj, f[j*8+ko]);
    }
    float* ps = g_xs + soff + bt*CKD + c*8;
    float* pd = g_d         + bt*CKD + c*8;
    float2 r0=up2(acc[0]), r1=up2(acc[1]), r2=up2(acc[2]), r3=up2(acc[3]);
    float2 r4=up2(acc[4]), r5=up2(acc[5]), r6=up2(acc[6]), r7=up2(acc[7]);
    *(float4*)ps     = make_float4(r0.x,r1.x,r2.x,r3.x);
    *(float4*)(ps+4) = make_float4(r4.x,r5.x,r6.x,r7.x);
    *(float4*)pd     = make_float4(r0.y,r1.y,r2.y,r3.y);
    *(float4*)(pd+4) = make_float4(r4.y,r5.y,r6.y,r7.y);
}

// ---------------- reconstruction ----------------
__global__ void __launch_bounds__(256) k_recon(long xoff, long uoff,
        float* __restrict__ oext, long ooff,
        const float* __restrict__ rce, const float* __restrict__ rco, int nh){
    __shared__ ull f[128];
    if (threadIdx.x < 128) f[threadIdx.x] = pk2(rce[threadIdx.x], rco[threadIdx.x]);
    __syncthreads();
    long idx = blockIdx.x*(long)blockDim.x + threadIdx.x;
    if (idx >= (long)16*nh*16) return;
    int c = (int)(idx & 15);
    long bt = idx >> 4;
    const float* px = g_xs + xoff + bt*CKD + c*8;
    const float* pu = g_us + uoff + bt*CKD + c*8;
    const float* pw = g_ud + uoff + bt*CKD + c*8;
    float4 a0 = *(const float4*)px,     u0 = *(const float4*)pu;
    float4 a1 = *(const float4*)(px+4), u1 = *(const float4*)(pu+4);
    float4 w0 = *(const float4*)pw,     w1 = *(const float4*)(pw+4);
    float xc[16] = {a0.x+u0.x, a0.y+u0.y, a0.z+u0.z, a0.w+u0.w,
                    a1.x+u1.x, a1.y+u1.y, a1.z+u1.z, a1.w+u1.w,
                    w0.x, w0.y, w0.z, w0.w, w1.x, w1.y, w1.z, w1.w};
    ull acc[8];
    #pragma unroll
    for (int ko=0;ko<8;++ko) acc[ko]=0ull;
    #pragma unroll
    for (int j=0;j<16;++j){
        ull vj = pk2(xc[j], xc[j]);
        #pragma unroll
        for (int ko=0;ko<8;++ko) ffma2(acc[ko], vj, f[j*8+ko]);
    }
    float* po = (oext ? oext : (g_xs + ooff)) + bt*2*CKD + c*8;
    float2 r0=up2(acc[0]), r1=up2(acc[1]), r2=up2(acc[2]), r3=up2(acc[3]);
    float2 r4=up2(acc[4]), r5=up2(acc[5]), r6=up2(acc[6]), r7=up2(acc[7]);
    *(float4*)po         = make_float4(r0.x,r1.x,r2.x,r3.x);
    *(float4*)(po+4)     = make_float4(r4.x,r5.x,r6.x,r7.x);
    *(float4*)(po+CKD)   = make_float4(r0.y,r1.y,r2.y,r3.y);
    *(float4*)(po+CKD+4) = make_float4(r4.y,r5.y,r6.y,r7.y);
}

// ---------------- folded forward DFT: 16 modes, 2 ck/thread, 2 batches/block ----------------
// grid: (ceil(l/16), ssp, 16). z = bpair + 8*src.
#define FD_GRP(V0, V1, GBASE) { \
    _Pragma("unroll") \
    for (int i=0;i<4;++i){ \
        V0[i] = *(const float2*)(p + (long)((GBASE)+i)*CKD); \
        V1[i] = *(const float2*)(q + (long)((GBASE)+i)*CKD); \
    } }
#define FD_CMP(V0, V1, SLBASE) { \
    _Pragma("unroll") \
    for (int i=0;i<4;++i){ \
        float ax = V0[i].x + V1[i].x, ay = V0[i].y + V1[i].y; \
        float dx = V0[i].x - V1[i].x, dy = V0[i].y - V1[i].y; \
        ull a0 = pk2(ax,ax), a1 = pk2(ay,ay), d0 = pk2(dx,dx), d1 = pk2(dy,dy); \
        const ulonglong2* row = &stw[((SLBASE)+i)*8]; \
        _Pragma("unroll") \
        for (int j=0;j<8;++j){ \
            ulonglong2 t = row[j]; \
            ffma2(acc[2*j][0],   a0, t.x); \
            ffma2(acc[2*j][1],   a1, t.x); \
            ffma2(acc[2*j+1][0], d0, t.y); \
            ffma2(acc[2*j+1][1], d1, t.y); \
        } \
    } }

__global__ void __launch_bounds__(128) k_fdft(long voff, int usepart,
        int n, int l, int stride){
    __shared__ ulonglong2 stw[64*8];
    int ck2  = threadIdx.x & 63;
    int half = threadIdx.x >> 6;
    int m0 = blockIdx.x * 16;
    int src = blockIdx.z >> 3;
    int b   = 2*(blockIdx.z & 7) + half;
    int n2 = n >> 1;
    const float* vsrc = src ? (g_xs + voff) : g_d;
    float2* dstdir = src ? g_ftx : g_ftd;
    if (n2 == 0){   // n==1: Y0 = v
        if (m0 == 0){
            float2 v = *(const float2*)(vsrc + (long)b*CKD + 2*ck2);
            ((float4*)(dstdir + (long)b*64*CKD))[ck2] = make_float4(v.x, 0.f, v.y, 0.f);
        }
        return;
    }
    int ssp = gridDim.y;
    int chunk = n2 / ssp;
    int s0 = blockIdx.y * chunk;
    const float* p = vsrc + ((long)b*n + s0)*CKD + 2*ck2;
    const float* q = p + (long)n2*CKD;
    ull acc[16][2];
    #pragma unroll
    for (int i=0;i<16;++i){ acc[i][0]=0ull; acc[i][1]=0ull; }

    for (int sb=0; sb<chunk; sb+=64){
        int tile = chunk - sb; if (tile > 64) tile = 64;
        for (int t = threadIdx.x; t < 64*8; t += 128){
            int sl = t >> 3, j = t & 7;
            int me = m0 + 2*j, mo = me + 1;
            float2 te = make_float2(0.f,0.f), to = make_float2(0.f,0.f);
            if (sl < tile){
                int s = s0 + sb + sl;
                if (me < l) te = g_tw[(me*s*stride) & 4095];
                if (mo < l) to = g_tw[(mo*s*stride) & 4095];
            }
            stw[t] = make_ulonglong2(pk2(te.x,te.y), pk2(to.x,to.y));
        }
        __syncthreads();
        if (tile == 64){
            float2 va0[4], va1[4], vb0[4], vb1[4];
            FD_GRP(va0, va1, sb);
            #pragma unroll
            for (int g=0; g<16; g+=2){
                FD_GRP(vb0, vb1, sb+(g+1)*4);
                FD_CMP(va0, va1, g*4);
                if (g+2 < 16) FD_GRP(va0, va1, sb+(g+2)*4);
                FD_CMP(vb0, vb1, (g+1)*4);
            }
        } else {
            for (int sl=0; sl<tile; ++sl){
                float2 v0 = *(const float2*)(p + (long)(sb+sl)*CKD);
                float2 v1 = *(const float2*)(q + (long)(sb+sl)*CKD);
                float ax = v0.x+v1.x, ay = v0.y+v1.y;
                float dx = v0.x-v1.x, dy = v0.y-v1.y;
                ull a0 = pk2(ax,ax), a1 = pk2(ay,ay), d0 = pk2(dx,dx), d1 = pk2(dy,dy);
                const ulonglong2* row = &stw[sl*8];
                #pragma unroll
                for (int j=0;j<8;++j){
                    ulonglong2 t = row[j];
                    ffma2(acc[2*j][0],   a0, t.x);
                    ffma2(acc[2*j][1],   a1, t.x);
                    ffma2(acc[2*j+1][0], d0, t.y);
                    ffma2(acc[2*j+1][1], d1, t.y);
                }
            }
        }
        __syncthreads();
    }
    float2* dst = usepart
        ? (g_part + ((long)(src*ssp + blockIdx.y)*16 + b)*64*CKD)
        : (dstdir + (long)b*64*CKD);
    #pragma unroll
    for (int ml=0; ml<16; ++ml){
        int m = m0 + ml;
        if (m < l){
            float2 r0 = up2(acc[ml][0]), r1 = up2(acc[ml][1]);
            *(float4*)((float*)(dst + (long)m*CKD + 2*ck2)) = make_float4(r0.x,r0.y,r1.x,r1.y);
        }
    }
}

// ---------------- reduce s-split partials ----------------
__global__ void k_ftred(int l, int ssp){
    long idx = blockIdx.x*(long)blockDim.x + threadIdx.x;
    if (idx >= (long)16*l*CKD) return;
    int src = blockIdx.y;
    int ck = (int)(idx & 127);
    long r = idx >> 7;
    int m = (int)(r % l);
    int b = (int)(r / l);
    float2 a = make_float2(0.f, 0.f);
    for (int sp=0; sp<ssp; ++sp){
        float2 p = g_part[((long)(src*ssp + sp)*16 + b)*64*CKD + (long)m*CKD + ck];
        a.x += p.x; a.y += p.y;
    }
    (src ? g_ftx : g_ftd)[((long)b*64 + m)*CKD + ck] = a;
}

// ---------------- merged mode mixing ----------------
__global__ void __launch_bounds__(128) k_mix(int l){
    __shared__ __align__(16) ull sda[128*4], sdb[128*4], sxa[128*4], sxb[128*4];
    int o = threadIdx.x;
    int m = blockIdx.x;
    int bg = blockIdx.y;
    #pragma unroll
    for (int j=0;j<4;++j){
        float2 f = g_ftd[((long)(bg*4+j)*64 + m)*CKD + o];
        sda[o*4+j] = pk2(f.x, f.x);
        sdb[o*4+j] = pk2(-f.y, f.y);
        float2 g = g_ftx[((long)(bg*4+j)*64 + m)*CKD + o];
        sxa[o*4+j] = pk2(g.x, g.x);
        sxb[o*4+j] = pk2(-g.y, g.y);
    }
    __syncthreads();
    const float2* wA = g_wt + (long)m*16384 + o;
    const float2* wB = wA + (long)64*16384;
    const float2* wC = wB + (long)64*16384;
    ull ud[4], us[4];
    #pragma unroll
    for (int j=0;j<4;++j){ ud[j]=0ull; us[j]=0ull; }
    #pragma unroll 2
    for (int i=0;i<128;++i){
        float2 a = wA[(long)i*CKD];
        float2 b = wB[(long)i*CKD];
        float2 c = wC[(long)i*CKD];
        ull Ap = pk2(a.x, a.y), As = pk2(a.y, a.x);
        ull Bp = pk2(b.x, b.y), Bs = pk2(b.y, b.x);
        ull Cp = pk2(c.x, c.y), Cs = pk2(c.y, c.x);
        ulonglong2 d01 = *(const ulonglong2*)&sda[i*4];
        ulonglong2 d23 = *(const ulonglong2*)&sda[i*4+2];
        ulonglong2 e01 = *(const ulonglong2*)&sdb[i*4];
        ulonglong2 e23 = *(const ulonglong2*)&sdb[i*4+2];
        ulonglong2 x01 = *(const ulonglong2*)&sxa[i*4];
        ulonglong2 x23 = *(const ulonglong2*)&sxa[i*4+2];
        ulonglong2 y01 = *(const ulonglong2*)&sxb[i*4];
        ulonglong2 y23 = *(const ulonglong2*)&sxb[i*4+2];
        ffma2(ud[0], d01.x, Ap); ffma2(ud[0], e01.x, As);
        ffma2(ud[0], x01.x, Bp); ffma2(ud[0], y01.x, Bs);
        ffma2(us[0], d01.x, Cp); ffma2(us[0], e01.x, Cs);
        ffma2(ud[1], d01.y, Ap); ffma2(ud[1], e01.y, As);
        ffma2(ud[1], x01.y, Bp); ffma2(ud[1], y01.y, Bs);
        ffma2(us[1], d01.y, Cp); ffma2(us[1], e01.y, Cs);
        ffma2(ud[2], d23.x, Ap); ffma2(ud[2], e23.x, As);
        ffma2(ud[2], x23.x, Bp); ffma2(ud[2], y23.x, Bs);
        ffma2(us[2], d23.x, Cp); ffma2(us[2], e23.x, Cs);
        ffma2(ud[3], d23.y, Ap); ffma2(ud[3], e23.y, As);
        ffma2(ud[3], x23.y, Bp); ffma2(ud[3], y23.y, Bs);
        ffma2(us[3], d23.y, Cp); ffma2(us[3], e23.y, Cs);
    }
    #pragma unroll
    for (int j=0;j<4;++j){
        g_oud[((long)(bg*4+j)*64 + m)*CKD + o] = up2(ud[j]);
        g_ous[((long)(bg*4+j)*64 + m)*CKD + o] = up2(us[j]);
    }
}

// ---------------- folded inverse DFT, parity-split halves, (ud,us) lane-packed ----------------
// block 256 = 128 ck x 2 parity. E-half stashes, O-half combines & stores.
__global__ void __launch_bounds__(256) k_idft(long uoff, int n, int l, int stride, float invn){
    __shared__ ulonglong2 tab[64*16];
    __shared__ ull stash[16*128];
    int ck = threadIdx.x & 127;
    int parity = threadIdx.x >> 7;
    int b  = blockIdx.y;
    int n2 = n >> 1;
    if (n2 == 0){
        if (parity == 0){
            float2 yd = g_oud[(long)b*64*CKD + ck];
            float2 ys = g_ous[(long)b*64*CKD + ck];
            g_ud[uoff + (long)b*CKD + ck] = yd.x;
            g_us[uoff + (long)b*CKD + ck] = ys.x;
        }
        return;
    }
    int tb = blockIdx.x * 16;
    for (int q = threadIdx.x; q < l*16; q += 256){
        int m = q >> 4, tp = q & 15;
        int t = tb + tp;
        float2 e = make_float2(0.f, 0.f);
        float sc = 0.f;
        if (t < n2){
            e = g_tw[(m*t*stride) & 4095];
            sc = ((m==0) || (2*m==n)) ? invn : 2.f*invn;
        }
        tab[q] = make_ulonglong2(pk2(sc*e.x, sc*e.x), pk2(sc*e.y, sc*e.y));
    }
    __syncthreads();
    const float2* pod = g_oud + (long)b*64*CKD + ck;
    const float2* pos = g_ous + (long)b*64*CKD + ck;
    ull acc[16];
    #pragma unroll
    for (int i=0;i<16;++i) acc[i]=0ull;
    int mcount = (l - parity + 1) >> 1;
    if (mcount > 0){
        float2 yd = pod[(long)parity*CKD], ys = pos[(long)parity*CKD];
        for (int k=0; k<mcount; ++k){
            int m = parity + 2*k;
            float2 ydn = make_float2(0.f,0.f), ysn = make_float2(0.f,0.f);
            if (k+1 < mcount){
                ydn = pod[(long)(m+2)*CKD];
                ysn = pos[(long)(m+2)*CKD];
            }
            ull re2 = pk2(yd.x, ys.x);
            ull im2 = pk2(yd.y, ys.y);
            const ulonglong2* row = &tab[m*16];
            #pragma unroll
            for (int tp=0; tp<16; ++tp){
                ulonglong2 t = row[tp];
                ffma2(acc[tp], re2, t.x);
                ffma2(acc[tp], im2, t.y);
            }
            yd = ydn; ys = ysn;
        }
    }
    if (parity == 0){
        #pragma unroll
        for (int tp=0; tp<16; ++tp) stash[tp*128 + ck] = acc[tp];
    }
    __syncthreads();
    if (parity == 1){
        float* pud = g_ud + uoff + (long)b*n*CKD + ck;
        float* pus = g_us + uoff + (long)b*n*CKD + ck;
        #pragma unroll
        for (int tp=0; tp<16; ++tp){
            int t = tb + tp;
            if (t < n2){
                float2 E = up2(stash[tp*128 + ck]), O = up2(acc[tp]);
                pud[(long)t*CKD]      = E.x + O.x;
                pus[(long)t*CKD]      = E.y + O.y;
                pud[(long)(t+n2)*CKD] = E.x - O.x;
                pus[(long)(t+n2)*CKD] = E.y - O.y;
            }
        }
    }
}

// ---------------- LayerNorm + exact GELU ----------------
__global__ void k_lngelu(const float* __restrict__ w, const float* __restrict__ bia, long off){
    int b = blockIdx.x, t = threadIdx.x;
    __shared__ float rs[8];
    float v = g_xs[off + (long)b*CKD + t];
    float s1 = v, s2 = v*v;
    #pragma unroll
    for (int o=16; o; o>>=1){
        s1 += __shfl_xor_sync(0xffffffffu, s1, o);
        s2 += __shfl_xor_sync(0xffffffffu, s2, o);
    }
    if ((t & 31) == 0){ rs[t>>5] = s1; rs[4+(t>>5)] = s2; }
    __syncthreads();
    float m1 = (rs[0]+rs[1]+rs[2]+rs[3]) * (1.0f/128.0f);
    float m2 = (rs[4]+rs[5]+rs[6]+rs[7]) * (1.0f/128.0f);
    float var = m2 - m1*m1;
    float xn = (v - m1) * rsqrtf(var + 1e-5f) * w[t] + bia[t];
    float ge = 0.5f * xn * (1.0f + erff(xn * 0.70710678118654752f));
    g_xs[off + (long)b*CKD + t] = ge;
}

// ---------------- host ----------------
extern "C" void kernel_launch(void* const* d_in, const int* in_sizes, int n_in,
                              void* d_out, int out_size) {
    const float* x   = (const float*)d_in[0];
    const float* Awr = (const float*)d_in[1];
    const float* Awi = (const float*)d_in[2];
    const float* Bwr = (const float*)d_in[3];
    const float* Bwi = (const float*)d_in[4];
    const float* Cwr = (const float*)d_in[5];
    const float* Cwi = (const float*)d_in[6];
    const float* lnw = (const float*)d_in[7];
    const float* lnb = (const float*)d_in[8];
    const float* ecs = (const float*)d_in[9];
    const float* ecd = (const float*)d_in[10];
    const float* rce = (const float*)d_in[11];
    const float* rco = (const float*)d_in[12];
    float* out = (float*)d_out;

    static const int NH[13]  = {4096,2048,1024,512,256,128,64,32,16,8,4,2,1};
    static const int LM[13]  = {64,64,64,64,64,64,33,17,9,5,3,2,1};
    static const int SSP[13] = {16,16,8,4,2,1,1,1,1,1,1,1,1};
    long OFF[13];
    OFF[0] = 0;
    for (int l=1; l<13; ++l) OFF[l] = OFF[l-1] + (long)16*NH[l-1]*128;

    k_base<<<16, 256>>>();
    long wthr = (long)3*64*128*128;
    k_wtrans<<<(unsigned)((wthr+255)/256), 256>>>(Awr, Awi, Bwr, Bwi, Cwr, Cwi);

    for (int l=0; l<13; ++l){
        int nh = NH[l], lm = LM[l], ssp = SSP[l], stride = 4096 / nh;
        long nthr = (long)16*nh*16;
        unsigned blk = (unsigned)((nthr + 255) / 256);
        k_decompose<<<blk, 256>>>(l==0 ? x : (const float*)0, l ? OFF[l-1] : 0,
                                  OFF[l], ecs, ecd, nh);
        dim3 gf((lm+15)/16, ssp, 16);
        k_fdft<<<gf, 128>>>(OFF[l], ssp>1 ? 1 : 0, nh, lm, stride);
        if (ssp > 1){
            unsigned rb = (unsigned)(((long)16*lm*128 + 255)/256);
            k_ftred<<<dim3(rb, 2), 256>>>(lm, ssp);
        }
        k_mix<<<dim3(lm, 4), 128>>>(lm);
        int n2 = nh >> 1;
        int gx = (n2 == 0) ? 1 : (n2 + 15)/16;
        k_idft<<<dim3(gx, 16), 256>>>(OFF[l], nh, lm, stride, 1.0f/(float)nh);
    }

    k_lngelu<<<16, 128>>>(lnw, lnb, OFF[12]);

    for (int l=12; l>=0; --l){
        int nh = NH[l];
        long nthr = (long)16*nh*16;
        unsigned blk = (unsigned)((nthr + 255) / 256);
        k_recon<<<blk, 256>>>(OFF[l], OFF[l],
                              l ? (float*)0 : out, l ? OFF[l-1] : 0,
                              rce, rco, nh);
    }
}

// round 6
// speedup vs baseline: 1.1144x; 1.1144x over previous
#include <cuda_runtime.h>
#include <cuda_bf16.h>

#define CKD 128
typedef unsigned long long ull;

// ---------------- static scratch ----------------
__device__ float  g_xs[(long)16*8191*128];
__device__ float  g_d [(long)16*4096*128];
__device__ float  g_ud[(long)16*8191*128];
__device__ float  g_us[(long)16*8191*128];
__device__ float2 g_part[(long)2*16*16*64*128];
__device__ float2 g_ftd[16*64*128];
__device__ float2 g_ftx[16*64*128];
__device__ float2 g_oud[16*64*128];
__device__ float2 g_ous[16*64*128];
__device__ float2 g_wt[(long)3*64*128*128];
__device__ float2 g_tw[4096+64];

// ---------------- f32x2 helpers ----------------
__device__ __forceinline__ ull pk2(float x, float y){
    ull r; asm("mov.b64 %0, {%1, %2};" : "=l"(r) : "f"(x), "f"(y)); return r;
}
__device__ __forceinline__ float2 up2(ull v){
    float2 r; asm("mov.b64 {%0, %1}, %2;" : "=f"(r.x), "=f"(r.y) : "l"(v)); return r;
}
__device__ __forceinline__ void ffma2(ull &acc, ull a, ull b){
    asm("fma.rn.f32x2 %0, %1, %2, %0;" : "+l"(acc) : "l"(a), "l"(b));
}

// ---------------- base twiddle table ----------------
__global__ void k_base(){
    int r = blockIdx.x*blockDim.x + threadIdx.x;
    if (r >= 4096) return;
    float s, c;
    sincospif(r/2048.0f, &s, &c);
    g_tw[r] = make_float2(c, -s);
    if (r < 64) g_tw[4096+r] = make_float2(0.f, 0.f);
}

// ---------------- weight transpose (i,o,m) -> (m,i,o), all 3 matrices ----------------
__global__ void k_wtrans(const float* __restrict__ Ar, const float* __restrict__ Ai,
                         const float* __restrict__ Br, const float* __restrict__ Bi,
                         const float* __restrict__ Cr, const float* __restrict__ Ci){
    long gidx = blockIdx.x*(long)blockDim.x + threadIdx.x;
    const long per = (long)64*128*128;
    if (gidx >= 3*per) return;
    int mat = (int)(gidx / per);
    long idx = gidx - (long)mat*per;
    const float* wr = mat==0 ? Ar : (mat==1 ? Br : Cr);
    const float* wi = mat==0 ? Ai : (mat==1 ? Bi : Ci);
    int m = (int)(idx & 63);
    int o = (int)((idx >> 6) & 127);
    int i = (int)(idx >> 13);
    g_wt[((long)mat*64 + m)*16384 + (long)i*128 + o] = make_float2(wr[idx], wi[idx]);
}

// ---------------- wavelet decompose ----------------
__global__ void __launch_bounds__(256) k_decompose(const float* __restrict__ xext, long xoff,
        long soff, const float* __restrict__ ecs, const float* __restrict__ ecd, int nh){
    __shared__ ull f[128];
    if (threadIdx.x < 128) f[threadIdx.x] = pk2(ecs[threadIdx.x], ecd[threadIdx.x]);
    __syncthreads();
    long idx = blockIdx.x*(long)blockDim.x + threadIdx.x;
    if (idx >= (long)16*nh*16) return;
    int c = (int)(idx & 15);
    long bt = idx >> 4;
    const float* xin = xext ? xext : (g_xs + xoff);
    const float* pe = xin + bt*2*CKD + c*8;
    float4 e0 = *(const float4*)(pe);
    float4 e1 = *(const float4*)(pe+4);
    float4 o0 = *(const float4*)(pe+CKD);
    float4 o1 = *(const float4*)(pe+CKD+4);
    float xa[16] = {e0.x,e0.y,e0.z,e0.w, e1.x,e1.y,e1.z,e1.w,
                    o0.x,o0.y,o0.z,o0.w, o1.x,o1.y,o1.z,o1.w};
    ull acc[8];
    #pragma unroll
    for (int ko=0;ko<8;++ko) acc[ko]=0ull;
    #pragma unroll
    for (int j=0;j<16;++j){
        ull vj = pk2(xa[j], xa[j]);
        #pragma unroll
        for (int ko=0;ko<8;++ko) ffma2(acc[ko], vj, f[j*8+ko]);
    }
    float* ps = g_xs + soff + bt*CKD + c*8;
    float* pd = g_d         + bt*CKD + c*8;
    float2 r0=up2(acc[0]), r1=up2(acc[1]), r2=up2(acc[2]), r3=up2(acc[3]);
    float2 r4=up2(acc[4]), r5=up2(acc[5]), r6=up2(acc[6]), r7=up2(acc[7]);
    *(float4*)ps     = make_float4(r0.x,r1.x,r2.x,r3.x);
    *(float4*)(ps+4) = make_float4(r4.x,r5.x,r6.x,r7.x);
    *(float4*)pd     = make_float4(r0.y,r1.y,r2.y,r3.y);
    *(float4*)(pd+4) = make_float4(r4.y,r5.y,r6.y,r7.y);
}

// ---------------- reconstruction ----------------
__global__ void __launch_bounds__(256) k_recon(long xoff, long uoff,
        float* __restrict__ oext, long ooff,
        const float* __restrict__ rce, const float* __restrict__ rco, int nh){
    __shared__ ull f[128];
    if (threadIdx.x < 128) f[threadIdx.x] = pk2(rce[threadIdx.x], rco[threadIdx.x]);
    __syncthreads();
    long idx = blockIdx.x*(long)blockDim.x + threadIdx.x;
    if (idx >= (long)16*nh*16) return;
    int c = (int)(idx & 15);
    long bt = idx >> 4;
    const float* px = g_xs + xoff + bt*CKD + c*8;
    const float* pu = g_us + uoff + bt*CKD + c*8;
    const float* pw = g_ud + uoff + bt*CKD + c*8;
    float4 a0 = *(const float4*)px,     u0 = *(const float4*)pu;
    float4 a1 = *(const float4*)(px+4), u1 = *(const float4*)(pu+4);
    float4 w0 = *(const float4*)pw,     w1 = *(const float4*)(pw+4);
    float xc[16] = {a0.x+u0.x, a0.y+u0.y, a0.z+u0.z, a0.w+u0.w,
                    a1.x+u1.x, a1.y+u1.y, a1.z+u1.z, a1.w+u1.w,
                    w0.x, w0.y, w0.z, w0.w, w1.x, w1.y, w1.z, w1.w};
    ull acc[8];
    #pragma unroll
    for (int ko=0;ko<8;++ko) acc[ko]=0ull;
    #pragma unroll
    for (int j=0;j<16;++j){
        ull vj = pk2(xc[j], xc[j]);
        #pragma unroll
        for (int ko=0;ko<8;++ko) ffma2(acc[ko], vj, f[j*8+ko]);
    }
    float* po = (oext ? oext : (g_xs + ooff)) + bt*2*CKD + c*8;
    float2 r0=up2(acc[0]), r1=up2(acc[1]), r2=up2(acc[2]), r3=up2(acc[3]);
    float2 r4=up2(acc[4]), r5=up2(acc[5]), r6=up2(acc[6]), r7=up2(acc[7]);
    *(float4*)po         = make_float4(r0.x,r1.x,r2.x,r3.x);
    *(float4*)(po+4)     = make_float4(r4.x,r5.x,r6.x,r7.x);
    *(float4*)(po+CKD)   = make_float4(r0.y,r1.y,r2.y,r3.y);
    *(float4*)(po+CKD+4) = make_float4(r4.y,r5.y,r6.y,r7.y);
}

// ---------------- folded forward DFT: 16 modes, 1 batch/block, depth-4 prefetch ----------------
// grid: (ceil(l/16), ssp, 32). z = b + 16*src.
__global__ void __launch_bounds__(128) k_fdft(long voff, int usepart,
        int n, int l, int stride){
    __shared__ ulonglong2 stw[64*8];
    int ck = threadIdx.x;
    int m0 = blockIdx.x * 16;
    int src = blockIdx.z >> 4;
    int b   = blockIdx.z & 15;
    int n2 = n >> 1;
    const float* vsrc = src ? (g_xs + voff) : g_d;
    float2* dstdir = src ? g_ftx : g_ftd;
    if (n2 == 0){   // n==1: Y0 = v
        if (m0 == 0){
            float v = vsrc[(long)b*CKD + ck];
            dstdir[((long)b*64)*CKD + ck] = make_float2(v, 0.f);
        }
        return;
    }
    int ssp = gridDim.y;
    int chunk = n2 / ssp;
    int s0 = blockIdx.y * chunk;
    const float* p = vsrc + ((long)b*n + s0)*CKD + ck;
    const float* q = p + (long)n2*CKD;
    ull acc[16];
    #pragma unroll
    for (int i=0;i<16;++i) acc[i]=0ull;

    for (int sb=0; sb<chunk; sb+=64){
        int tile = chunk - sb; if (tile > 64) tile = 64;
        for (int t = threadIdx.x; t < 64*8; t += 128){
            int sl = t >> 3, j = t & 7;
            int me = m0 + 2*j, mo = me + 1;
            float2 te = make_float2(0.f,0.f), to = make_float2(0.f,0.f);
            if (sl < tile){
                int s = s0 + sb + sl;
                if (me < l) te = g_tw[(me*s*stride) & 4095];
                if (mo < l) to = g_tw[(mo*s*stride) & 4095];
            }
            stw[t] = make_ulonglong2(pk2(te.x,te.y), pk2(to.x,to.y));
        }
        __syncthreads();
        if (tile == 64){
            // 16 groups of 4 s-values, double-buffered (depth-4 prefetch)
            float r0[4], r1[4], u0[4], u1[4];
            #pragma unroll
            for (int i=0;i<4;++i){
                r0[i] = p[(long)(sb+i)*CKD];
                r1[i] = q[(long)(sb+i)*CKD];
            }
            #pragma unroll
            for (int g=0; g<16; g+=2){
                #pragma unroll
                for (int i=0;i<4;++i){
                    u0[i] = p[(long)(sb+(g+1)*4+i)*CKD];
                    u1[i] = q[(long)(sb+(g+1)*4+i)*CKD];
                }
                #pragma unroll
                for (int i=0;i<4;++i){
                    float a = r0[i]+r1[i], d = r0[i]-r1[i];
                    ull ap = pk2(a,a), dp = pk2(d,d);
                    const ulonglong2* row = &stw[(g*4+i)*8];
                    #pragma unroll
                    for (int j=0;j<8;++j){
                        ulonglong2 t = row[j];
                        ffma2(acc[2*j],   ap, t.x);
                        ffma2(acc[2*j+1], dp, t.y);
                    }
                }
                if (g+2 < 16){
                    #pragma unroll
                    for (int i=0;i<4;++i){
                        r0[i] = p[(long)(sb+(g+2)*4+i)*CKD];
                        r1[i] = q[(long)(sb+(g+2)*4+i)*CKD];
                    }
                }
                #pragma unroll
                for (int i=0;i<4;++i){
                    float a = u0[i]+u1[i], d = u0[i]-u1[i];
                    ull ap = pk2(a,a), dp = pk2(d,d);
                    const ulonglong2* row = &stw[((g+1)*4+i)*8];
                    #pragma unroll
                    for (int j=0;j<8;++j){
                        ulonglong2 t = row[j];
                        ffma2(acc[2*j],   ap, t.x);
                        ffma2(acc[2*j+1], dp, t.y);
                    }
                }
            }
        } else {
            for (int sl=0; sl<tile; ++sl){
                float v0 = p[(long)(sb+sl)*CKD];
                float v1 = q[(long)(sb+sl)*CKD];
                ull a = pk2(v0+v1, v0+v1);
                ull d = pk2(v0-v1, v0-v1);
                const ulonglong2* row = &stw[sl*8];
                #pragma unroll
                for (int j=0;j<8;++j){
                    ulonglong2 t = row[j];
                    ffma2(acc[2*j],   a, t.x);
                    ffma2(acc[2*j+1], d, t.y);
                }
            }
        }
        __syncthreads();
    }
    float2* dst = usepart
        ? (g_part + ((long)(src*gridDim.y + blockIdx.y)*16 + b)*64*CKD)
        : (dstdir + (long)b*64*CKD);
    #pragma unroll
    for (int ml=0; ml<16; ++ml){
        int m = m0 + ml;
        if (m < l) dst[(long)m*CKD + ck] = up2(acc[ml]);
    }
}

// ---------------- reduce s-split partials ----------------
__global__ void k_ftred(int l, int ssp){
    long idx = blockIdx.x*(long)blockDim.x + threadIdx.x;
    if (idx >= (long)16*l*CKD) return;
    int src = blockIdx.y;
    int ck = (int)(idx & 127);
    long r = idx >> 7;
    int m = (int)(r % l);
    int b = (int)(r / l);
    float2 a = make_float2(0.f, 0.f);
    for (int sp=0; sp<ssp; ++sp){
        float2 p = g_part[((long)(src*ssp + sp)*16 + b)*64*CKD + (long)m*CKD + ck];
        a.x += p.x; a.y += p.y;
    }
    (src ? g_ftx : g_ftd)[((long)b*64 + m)*CKD + ck] = a;
}

// ---------------- merged mode mixing ----------------
__global__ void __launch_bounds__(128) k_mix(int l){
    __shared__ __align__(16) ull sda[128*4], sdb[128*4], sxa[128*4], sxb[128*4];
    int o = threadIdx.x;
    int m = blockIdx.x;
    int bg = blockIdx.y;
    #pragma unroll
    for (int j=0;j<4;++j){
        float2 f = g_ftd[((long)(bg*4+j)*64 + m)*CKD + o];
        sda[o*4+j] = pk2(f.x, f.x);
        sdb[o*4+j] = pk2(-f.y, f.y);
        float2 g = g_ftx[((long)(bg*4+j)*64 + m)*CKD + o];
        sxa[o*4+j] = pk2(g.x, g.x);
        sxb[o*4+j] = pk2(-g.y, g.y);
    }
    __syncthreads();
    const float2* wA = g_wt + (long)m*16384 + o;
    const float2* wB = wA + (long)64*16384;
    const float2* wC = wB + (long)64*16384;
    ull ud[4], us[4];
    #pragma unroll
    for (int j=0;j<4;++j){ ud[j]=0ull; us[j]=0ull; }
    #pragma unroll 2
    for (int i=0;i<128;++i){
        float2 a = wA[(long)i*CKD];
        float2 b = wB[(long)i*CKD];
        float2 c = wC[(long)i*CKD];
        ull Ap = pk2(a.x, a.y), As = pk2(a.y, a.x);
        ull Bp = pk2(b.x, b.y), Bs = pk2(b.y, b.x);
        ull Cp = pk2(c.x, c.y), Cs = pk2(c.y, c.x);
        ulonglong2 d01 = *(const ulonglong2*)&sda[i*4];
        ulonglong2 d23 = *(const ulonglong2*)&sda[i*4+2];
        ulonglong2 e01 = *(const ulonglong2*)&sdb[i*4];
        ulonglong2 e23 = *(const ulonglong2*)&sdb[i*4+2];
        ulonglong2 x01 = *(const ulonglong2*)&sxa[i*4];
        ulonglong2 x23 = *(const ulonglong2*)&sxa[i*4+2];
        ulonglong2 y01 = *(const ulonglong2*)&sxb[i*4];
        ulonglong2 y23 = *(const ulonglong2*)&sxb[i*4+2];
        ffma2(ud[0], d01.x, Ap); ffma2(ud[0], e01.x, As);
        ffma2(ud[0], x01.x, Bp); ffma2(ud[0], y01.x, Bs);
        ffma2(us[0], d01.x, Cp); ffma2(us[0], e01.x, Cs);
        ffma2(ud[1], d01.y, Ap); ffma2(ud[1], e01.y, As);
        ffma2(ud[1], x01.y, Bp); ffma2(ud[1], y01.y, Bs);
        ffma2(us[1], d01.y, Cp); ffma2(us[1], e01.y, Cs);
        ffma2(ud[2], d23.x, Ap); ffma2(ud[2], e23.x, As);
        ffma2(ud[2], x23.x, Bp); ffma2(ud[2], y23.x, Bs);
        ffma2(us[2], d23.x, Cp); ffma2(us[2], e23.x, Cs);
        ffma2(ud[3], d23.y, Ap); ffma2(ud[3], e23.y, As);
        ffma2(ud[3], x23.y, Bp); ffma2(ud[3], y23.y, Bs);
        ffma2(us[3], d23.y, Cp); ffma2(us[3], e23.y, Cs);
    }
    #pragma unroll
    for (int j=0;j<4;++j){
        g_oud[((long)(bg*4+j)*64 + m)*CKD + o] = up2(ud[j]);
        g_ous[((long)(bg*4+j)*64 + m)*CKD + o] = up2(us[j]);
    }
}

// ---------------- folded inverse DFT, parity-split halves, (ud,us) lane-packed ----------------
__global__ void __launch_bounds__(256) k_idft(long uoff, int n, int l, int stride, float invn){
    __shared__ ulonglong2 tab[64*16];
    __shared__ ull stash[16*128];
    int ck = threadIdx.x & 127;
    int parity = threadIdx.x >> 7;
    int b  = blockIdx.y;
    int n2 = n >> 1;
    if (n2 == 0){
        if (parity == 0){
            float2 yd = g_oud[(long)b*64*CKD + ck];
            float2 ys = g_ous[(long)b*64*CKD + ck];
            g_ud[uoff + (long)b*CKD + ck] = yd.x;
            g_us[uoff + (long)b*CKD + ck] = ys.x;
        }
        return;
    }
    int tb = blockIdx.x * 16;
    for (int q = threadIdx.x; q < l*16; q += 256){
        int m = q >> 4, tp = q & 15;
        int t = tb + tp;
        float2 e = make_float2(0.f, 0.f);
        float sc = 0.f;
        if (t < n2){
            e = g_tw[(m*t*stride) & 4095];
            sc = ((m==0) || (2*m==n)) ? invn : 2.f*invn;
        }
        tab[q] = make_ulonglong2(pk2(sc*e.x, sc*e.x), pk2(sc*e.y, sc*e.y));
    }
    __syncthreads();
    const float2* pod = g_oud + (long)b*64*CKD + ck;
    const float2* pos = g_ous + (long)b*64*CKD + ck;
    ull acc[16];
    #pragma unroll
    for (int i=0;i<16;++i) acc[i]=0ull;
    int mcount = (l - parity + 1) >> 1;
    if (mcount > 0){
        float2 yd = pod[(long)parity*CKD], ys = pos[(long)parity*CKD];
        for (int k=0; k<mcount; ++k){
            int m = parity + 2*k;
            float2 ydn = make_float2(0.f,0.f), ysn = make_float2(0.f,0.f);
            if (k+1 < mcount){
                ydn = pod[(long)(m+2)*CKD];
                ysn = pos[(long)(m+2)*CKD];
            }
            ull re2 = pk2(yd.x, ys.x);
            ull im2 = pk2(yd.y, ys.y);
            const ulonglong2* row = &tab[m*16];
            #pragma unroll
            for (int tp=0; tp<16; ++tp){
                ulonglong2 t = row[tp];
                ffma2(acc[tp], re2, t.x);
                ffma2(acc[tp], im2, t.y);
            }
            yd = ydn; ys = ysn;
        }
    }
    if (parity == 0){
        #pragma unroll
        for (int tp=0; tp<16; ++tp) stash[tp*128 + ck] = acc[tp];
    }
    __syncthreads();
    if (parity == 1){
        float* pud = g_ud + uoff + (long)b*n*CKD + ck;
        float* pus = g_us + uoff + (long)b*n*CKD + ck;
        #pragma unroll
        for (int tp=0; tp<16; ++tp){
            int t = tb + tp;
            if (t < n2){
                float2 E = up2(stash[tp*128 + ck]), O = up2(acc[tp]);
                pud[(long)t*CKD]      = E.x + O.x;
                pus[(long)t*CKD]      = E.y + O.y;
                pud[(long)(t+n2)*CKD] = E.x - O.x;
                pus[(long)(t+n2)*CKD] = E.y - O.y;
            }
        }
    }
}

// ---------------- LayerNorm + exact GELU ----------------
__global__ void k_lngelu(const float* __restrict__ w, const float* __restrict__ bia, long off){
    int b = blockIdx.x, t = threadIdx.x;
    __shared__ float rs[8];
    float v = g_xs[off + (long)b*CKD + t];
    float s1 = v, s2 = v*v;
    #pragma unroll
    for (int o=16; o; o>>=1){
        s1 += __shfl_xor_sync(0xffffffffu, s1, o);
        s2 += __shfl_xor_sync(0xffffffffu, s2, o);
    }
    if ((t & 31) == 0){ rs[t>>5] = s1; rs[4+(t>>5)] = s2; }
    __syncthreads();
    float m1 = (rs[0]+rs[1]+rs[2]+rs[3]) * (1.0f/128.0f);
    float m2 = (rs[4]+rs[5]+rs[6]+rs[7]) * (1.0f/128.0f);
    float var = m2 - m1*m1;
    float xn = (v - m1) * rsqrtf(var + 1e-5f) * w[t] + bia[t];
    float ge = 0.5f * xn * (1.0f + erff(xn * 0.70710678118654752f));
    g_xs[off + (long)b*CKD + t] = ge;
}

// ---------------- host ----------------
extern "C" void kernel_launch(void* const* d_in, const int* in_sizes, int n_in,
                              void* d_out, int out_size) {
    const float* x   = (const float*)d_in[0];
    const float* Awr = (const float*)d_in[1];
    const float* Awi = (const float*)d_in[2];
    const float* Bwr = (const float*)d_in[3];
    const float* Bwi = (const float*)d_in[4];
    const float* Cwr = (const float*)d_in[5];
    const float* Cwi = (const float*)d_in[6];
    const float* lnw = (const float*)d_in[7];
    const float* lnb = (const float*)d_in[8];
    const float* ecs = (const float*)d_in[9];
    const float* ecd = (const float*)d_in[10];
    const float* rce = (const float*)d_in[11];
    const float* rco = (const float*)d_in[12];
    float* out = (float*)d_out;

    static const int NH[13]  = {4096,2048,1024,512,256,128,64,32,16,8,4,2,1};
    static const int LM[13]  = {64,64,64,64,64,64,33,17,9,5,3,2,1};
    static const int SSP[13] = {16,16,8,4,2,1,1,1,1,1,1,1,1};
    long OFF[13];
    OFF[0] = 0;
    for (int l=1; l<13; ++l) OFF[l] = OFF[l-1] + (long)16*NH[l-1]*128;

    k_base<<<16, 256>>>();
    long wthr = (long)3*64*128*128;
    k_wtrans<<<(unsigned)((wthr+255)/256), 256>>>(Awr, Awi, Bwr, Bwi, Cwr, Cwi);

    for (int l=0; l<13; ++l){
        int nh = NH[l], lm = LM[l], ssp = SSP[l], stride = 4096 / nh;
        long nthr = (long)16*nh*16;
        unsigned blk = (unsigned)((nthr + 255) / 256);
        k_decompose<<<blk, 256>>>(l==0 ? x : (const float*)0, l ? OFF[l-1] : 0,
                                  OFF[l], ecs, ecd, nh);
        dim3 gf((lm+15)/16, ssp, 32);
        k_fdft<<<gf, 128>>>(OFF[l], ssp>1 ? 1 : 0, nh, lm, stride);
        if (ssp > 1){
            unsigned rb = (unsigned)(((long)16*lm*128 + 255)/256);
            k_ftred<<<dim3(rb, 2), 256>>>(lm, ssp);
        }
        k_mix<<<dim3(lm, 4), 128>>>(lm);
        int n2 = nh >> 1;
        int gx = (n2 == 0) ? 1 : (n2 + 15)/16;
        k_idft<<<dim3(gx, 16), 256>>>(OFF[l], nh, lm, stride, 1.0f/(float)nh);
    }

    k_lngelu<<<16, 128>>>(lnw, lnb, OFF[12]);

    for (int l=12; l>=0; --l){
        int nh = NH[l];
        long nthr = (long)16*nh*16;
        unsigned blk = (unsigned)((nthr + 255) / 256);
        k_recon<<<blk, 256>>>(OFF[l], OFF[l],
                              l ? (float*)0 : out, l ? OFF[l-1] : 0,
                              rce, rco, nh);
    }
}

// round 7
// speedup vs baseline: 1.1346x; 1.0182x over previous
#include <cuda_runtime.h>
#include <cuda_bf16.h>

#define CKD 128
typedef unsigned long long ull;

// ---------------- static scratch ----------------
__device__ float  g_xs[(long)16*8191*128];
__device__ float  g_d [(long)16*4096*128];
__device__ float  g_ud[(long)16*8191*128];
__device__ float  g_us[(long)16*8191*128];
__device__ float2 g_part[(long)2*16*16*64*128];
__device__ float2 g_ftd[16*64*128];
__device__ float2 g_ftx[16*64*128];
__device__ float2 g_oud[16*64*128];
__device__ float2 g_ous[16*64*128];
__device__ float2 g_wt[(long)3*64*128*128];
__device__ float2 g_tw[4096+64];

// ---------------- f32x2 helpers ----------------
__device__ __forceinline__ ull pk2(float x, float y){
    ull r; asm("mov.b64 %0, {%1, %2};" : "=l"(r) : "f"(x), "f"(y)); return r;
}
__device__ __forceinline__ float2 up2(ull v){
    float2 r; asm("mov.b64 {%0, %1}, %2;" : "=f"(r.x), "=f"(r.y) : "l"(v)); return r;
}
__device__ __forceinline__ void ffma2(ull &acc, ull a, ull b){
    asm("fma.rn.f32x2 %0, %1, %2, %0;" : "+l"(acc) : "l"(a), "l"(b));
}

// ---------------- base twiddle table ----------------
__global__ void k_base(){
    int r = blockIdx.x*blockDim.x + threadIdx.x;
    if (r >= 4096) return;
    float s, c;
    sincospif(r/2048.0f, &s, &c);
    g_tw[r] = make_float2(c, -s);
    if (r < 64) g_tw[4096+r] = make_float2(0.f, 0.f);
}

// ---------------- weight transpose (i,o,m) -> (m,i,o), all 3 matrices ----------------
__global__ void k_wtrans(const float* __restrict__ Ar, const float* __restrict__ Ai,
                         const float* __restrict__ Br, const float* __restrict__ Bi,
                         const float* __restrict__ Cr, const float* __restrict__ Ci){
    long gidx = blockIdx.x*(long)blockDim.x + threadIdx.x;
    const long per = (long)64*128*128;
    if (gidx >= 3*per) return;
    int mat = (int)(gidx / per);
    long idx = gidx - (long)mat*per;
    const float* wr = mat==0 ? Ar : (mat==1 ? Br : Cr);
    const float* wi = mat==0 ? Ai : (mat==1 ? Bi : Ci);
    int m = (int)(idx & 63);
    int o = (int)((idx >> 6) & 127);
    int i = (int)(idx >> 13);
    g_wt[((long)mat*64 + m)*16384 + (long)i*128 + o] = make_float2(wr[idx], wi[idx]);
}

// ---------------- wavelet decompose ----------------
__global__ void __launch_bounds__(256) k_decompose(const float* __restrict__ xext, long xoff,
        long soff, const float* __restrict__ ecs, const float* __restrict__ ecd, int nh){
    __shared__ ull f[128];
    if (threadIdx.x < 128) f[threadIdx.x] = pk2(ecs[threadIdx.x], ecd[threadIdx.x]);
    __syncthreads();
    long idx = blockIdx.x*(long)blockDim.x + threadIdx.x;
    if (idx >= (long)16*nh*16) return;
    int c = (int)(idx & 15);
    long bt = idx >> 4;
    const float* xin = xext ? xext : (g_xs + xoff);
    const float* pe = xin + bt*2*CKD + c*8;
    float4 e0 = *(const float4*)(pe);
    float4 e1 = *(const float4*)(pe+4);
    float4 o0 = *(const float4*)(pe+CKD);
    float4 o1 = *(const float4*)(pe+CKD+4);
    float xa[16] = {e0.x,e0.y,e0.z,e0.w, e1.x,e1.y,e1.z,e1.w,
                    o0.x,o0.y,o0.z,o0.w, o1.x,o1.y,o1.z,o1.w};
    ull acc[8];
    #pragma unroll
    for (int ko=0;ko<8;++ko) acc[ko]=0ull;
    #pragma unroll
    for (int j=0;j<16;++j){
        ull vj = pk2(xa[j], xa[j]);
        #pragma unroll
        for (int ko=0;ko<8;++ko) ffma2(acc[ko], vj, f[j*8+ko]);
    }
    float* ps = g_xs + soff + bt*CKD + c*8;
    float* pd = g_d         + bt*CKD + c*8;
    float2 r0=up2(acc[0]), r1=up2(acc[1]), r2=up2(acc[2]), r3=up2(acc[3]);
    float2 r4=up2(acc[4]), r5=up2(acc[5]), r6=up2(acc[6]), r7=up2(acc[7]);
    *(float4*)ps     = make_float4(r0.x,r1.x,r2.x,r3.x);
    *(float4*)(ps+4) = make_float4(r4.x,r5.x,r6.x,r7.x);
    *(float4*)pd     = make_float4(r0.y,r1.y,r2.y,r3.y);
    *(float4*)(pd+4) = make_float4(r4.y,r5.y,r6.y,r7.y);
}

// ---------------- reconstruction ----------------
__global__ void __launch_bounds__(256) k_recon(long xoff, long uoff,
        float* __restrict__ oext, long ooff,
        const float* __restrict__ rce, const float* __restrict__ rco, int nh){
    __shared__ ull f[128];
    if (threadIdx.x < 128) f[threadIdx.x] = pk2(rce[threadIdx.x], rco[threadIdx.x]);
    __syncthreads();
    long idx = blockIdx.x*(long)blockDim.x + threadIdx.x;
    if (idx >= (long)16*nh*16) return;
    int c = (int)(idx & 15);
    long bt = idx >> 4;
    const float* px = g_xs + xoff + bt*CKD + c*8;
    const float* pu = g_us + uoff + bt*CKD + c*8;
    const float* pw = g_ud + uoff + bt*CKD + c*8;
    float4 a0 = *(const float4*)px,     u0 = *(const float4*)pu;
    float4 a1 = *(const float4*)(px+4), u1 = *(const float4*)(pu+4);
    float4 w0 = *(const float4*)pw,     w1 = *(const float4*)(pw+4);
    float xc[16] = {a0.x+u0.x, a0.y+u0.y, a0.z+u0.z, a0.w+u0.w,
                    a1.x+u1.x, a1.y+u1.y, a1.z+u1.z, a1.w+u1.w,
                    w0.x, w0.y, w0.z, w0.w, w1.x, w1.y, w1.z, w1.w};
    ull acc[8];
    #pragma unroll
    for (int ko=0;ko<8;++ko) acc[ko]=0ull;
    #pragma unroll
    for (int j=0;j<16;++j){
        ull vj = pk2(xc[j], xc[j]);
        #pragma unroll
        for (int ko=0;ko<8;++ko) ffma2(acc[ko], vj, f[j*8+ko]);
    }
    float* po = (oext ? oext : (g_xs + ooff)) + bt*2*CKD + c*8;
    float2 r0=up2(acc[0]), r1=up2(acc[1]), r2=up2(acc[2]), r3=up2(acc[3]);
    float2 r4=up2(acc[4]), r5=up2(acc[5]), r6=up2(acc[6]), r7=up2(acc[7]);
    *(float4*)po         = make_float4(r0.x,r1.x,r2.x,r3.x);
    *(float4*)(po+4)     = make_float4(r4.x,r5.x,r6.x,r7.x);
    *(float4*)(po+CKD)   = make_float4(r0.y,r1.y,r2.y,r3.y);
    *(float4*)(po+CKD+4) = make_float4(r4.y,r5.y,r6.y,r7.y);
}

// ---------------- folded forward DFT: tile (8 modes x 2 ck)/thread ----------------
// block 128 = 2 mode-halves x 64 ck-pairs. grid: (ceil(l/16), ssp, 32). z = b + 16*src.
#define FDC(VR0, VR1, SL) { \
    float ax = VR0.x+VR1.x, ay = VR0.y+VR1.y; \
    float dx = VR0.x-VR1.x, dy = VR0.y-VR1.y; \
    ull a0 = pk2(ax,ax), a1 = pk2(ay,ay), d0 = pk2(dx,dx), d1 = pk2(dy,dy); \
    const ulonglong2* row_ = base + (SL)*4; \
    _Pragma("unroll") \
    for (int j_=0;j_<4;++j_){ \
        ulonglong2 t_ = row_[j_]; \
        ffma2(acc[j_*4+0], a0, t_.x); \
        ffma2(acc[j_*4+1], a1, t_.x); \
        ffma2(acc[j_*4+2], d0, t_.y); \
        ffma2(acc[j_*4+3], d1, t_.y); \
    } }

__global__ void __launch_bounds__(128) k_fdft(long voff, int usepart,
        int n, int l, int stride){
    __shared__ ulonglong2 stw[512];    // [(h*64+s)*4 + j]
    int tck = threadIdx.x & 63;
    int h   = threadIdx.x >> 6;
    int m0 = blockIdx.x * 16;
    int src = blockIdx.z >> 4;
    int b   = blockIdx.z & 15;
    int n2 = n >> 1;
    const float* vsrc = src ? (g_xs + voff) : g_d;
    float2* dstdir = src ? g_ftx : g_ftd;
    if (n2 == 0){   // n==1: Y0 = v
        if (m0 == 0 && h == 0){
            float2 v = *(const float2*)(vsrc + (long)b*CKD + 2*tck);
            *(float4*)((float*)(dstdir + (long)b*64*CKD + 2*tck)) = make_float4(v.x, 0.f, v.y, 0.f);
        }
        return;
    }
    int ssp = gridDim.y;
    int chunk = n2 / ssp;
    int s0 = blockIdx.y * chunk;
    const float2* p2 = (const float2*)(vsrc + ((long)b*n + s0)*CKD) + tck;
    const float2* q2 = p2 + (long)n2*64;
    ull acc[16];
    #pragma unroll
    for (int i=0;i<16;++i) acc[i]=0ull;

    for (int sb=0; sb<chunk; sb+=64){
        int tile = chunk - sb; if (tile > 64) tile = 64;
        for (int e = threadIdx.x; e < 512; e += 128){
            int eh = e >> 8, es = (e >> 2) & 63, ej = e & 3;
            int me = m0 + 8*eh + 2*ej, mo = me + 1;
            float2 te = make_float2(0.f,0.f), to = make_float2(0.f,0.f);
            if (es < tile){
                int s = s0 + sb + es;
                if (me < l) te = g_tw[(me*s*stride) & 4095];
                if (mo < l) to = g_tw[(mo*s*stride) & 4095];
            }
            stw[e] = make_ulonglong2(pk2(te.x,te.y), pk2(to.x,to.y));
        }
        __syncthreads();
        const ulonglong2* base = &stw[h*256];
        if ((tile & 7) == 0){
            int ng = tile >> 2;      // groups of 4, ng even
            float2 r0[4], r1[4], u0[4], u1[4];
            #pragma unroll
            for (int i=0;i<4;++i){
                r0[i] = p2[(long)(sb+i)*64];
                r1[i] = q2[(long)(sb+i)*64];
            }
            for (int g=0; g<ng; g+=2){
                #pragma unroll
                for (int i=0;i<4;++i){
                    u0[i] = p2[(long)(sb+(g+1)*4+i)*64];
                    u1[i] = q2[(long)(sb+(g+1)*4+i)*64];
                }
                #pragma unroll
                for (int i=0;i<4;++i) FDC(r0[i], r1[i], g*4+i);
                if (g+2 < ng){
                    #pragma unroll
                    for (int i=0;i<4;++i){
                        r0[i] = p2[(long)(sb+(g+2)*4+i)*64];
                        r1[i] = q2[(long)(sb+(g+2)*4+i)*64];
                    }
                }
                #pragma unroll
                for (int i=0;i<4;++i) FDC(u0[i], u1[i], (g+1)*4+i);
            }
        } else {
            for (int sl=0; sl<tile; ++sl){
                float2 v0 = p2[(long)(sb+sl)*64];
                float2 v1 = q2[(long)(sb+sl)*64];
                FDC(v0, v1, sl);
            }
        }
        __syncthreads();
    }
    float2* dst = usepart
        ? (g_part + ((long)(src*ssp + blockIdx.y)*16 + b)*64*CKD)
        : (dstdir + (long)b*64*CKD);
    #pragma unroll
    for (int j=0;j<4;++j){
        int me = m0 + 8*h + 2*j;
        if (me < l){
            float2 c0 = up2(acc[j*4+0]), c1 = up2(acc[j*4+1]);
            *(float4*)((float*)(dst + (long)me*CKD + 2*tck)) = make_float4(c0.x,c0.y,c1.x,c1.y);
        }
        if (me+1 < l){
            float2 c0 = up2(acc[j*4+2]), c1 = up2(acc[j*4+3]);
            *(float4*)((float*)(dst + (long)(me+1)*CKD + 2*tck)) = make_float4(c0.x,c0.y,c1.x,c1.y);
        }
    }
}

// ---------------- reduce s-split partials ----------------
__global__ void k_ftred(int l, int ssp){
    long idx = blockIdx.x*(long)blockDim.x + threadIdx.x;
    if (idx >= (long)16*l*CKD) return;
    int src = blockIdx.y;
    int ck = (int)(idx & 127);
    long r = idx >> 7;
    int m = (int)(r % l);
    int b = (int)(r / l);
    float2 a = make_float2(0.f, 0.f);
    for (int sp=0; sp<ssp; ++sp){
        float2 p = g_part[((long)(src*ssp + sp)*16 + b)*64*CKD + (long)m*CKD + ck];
        a.x += p.x; a.y += p.y;
    }
    (src ? g_ftx : g_ftd)[((long)b*64 + m)*CKD + ck] = a;
}

// ---------------- merged mode mixing ----------------
__global__ void __launch_bounds__(128) k_mix(int l){
    __shared__ __align__(16) ull sda[128*4], sdb[128*4], sxa[128*4], sxb[128*4];
    int o = threadIdx.x;
    int m = blockIdx.x;
    int bg = blockIdx.y;
    #pragma unroll
    for (int j=0;j<4;++j){
        float2 f = g_ftd[((long)(bg*4+j)*64 + m)*CKD + o];
        sda[o*4+j] = pk2(f.x, f.x);
        sdb[o*4+j] = pk2(-f.y, f.y);
        float2 g = g_ftx[((long)(bg*4+j)*64 + m)*CKD + o];
        sxa[o*4+j] = pk2(g.x, g.x);
        sxb[o*4+j] = pk2(-g.y, g.y);
    }
    __syncthreads();
    const float2* wA = g_wt + (long)m*16384 + o;
    const float2* wB = wA + (long)64*16384;
    const float2* wC = wB + (long)64*16384;
    ull ud[4], us[4];
    #pragma unroll
    for (int j=0;j<4;++j){ ud[j]=0ull; us[j]=0ull; }
    #pragma unroll 2
    for (int i=0;i<128;++i){
        float2 a = wA[(long)i*CKD];
        float2 b = wB[(long)i*CKD];
        float2 c = wC[(long)i*CKD];
        ull Ap = pk2(a.x, a.y), As = pk2(a.y, a.x);
        ull Bp = pk2(b.x, b.y), Bs = pk2(b.y, b.x);
        ull Cp = pk2(c.x, c.y), Cs = pk2(c.y, c.x);
        ulonglong2 d01 = *(const ulonglong2*)&sda[i*4];
        ulonglong2 d23 = *(const ulonglong2*)&sda[i*4+2];
        ulonglong2 e01 = *(const ulonglong2*)&sdb[i*4];
        ulonglong2 e23 = *(const ulonglong2*)&sdb[i*4+2];
        ulonglong2 x01 = *(const ulonglong2*)&sxa[i*4];
        ulonglong2 x23 = *(const ulonglong2*)&sxa[i*4+2];
        ulonglong2 y01 = *(const ulonglong2*)&sxb[i*4];
        ulonglong2 y23 = *(const ulonglong2*)&sxb[i*4+2];
        ffma2(ud[0], d01.x, Ap); ffma2(ud[0], e01.x, As);
        ffma2(ud[0], x01.x, Bp); ffma2(ud[0], y01.x, Bs);
        ffma2(us[0], d01.x, Cp); ffma2(us[0], e01.x, Cs);
        ffma2(ud[1], d01.y, Ap); ffma2(ud[1], e01.y, As);
        ffma2(ud[1], x01.y, Bp); ffma2(ud[1], y01.y, Bs);
        ffma2(us[1], d01.y, Cp); ffma2(us[1], e01.y, Cs);
        ffma2(ud[2], d23.x, Ap); ffma2(ud[2], e23.x, As);
        ffma2(ud[2], x23.x, Bp); ffma2(ud[2], y23.x, Bs);
        ffma2(us[2], d23.x, Cp); ffma2(us[2], e23.x, Cs);
        ffma2(ud[3], d23.y, Ap); ffma2(ud[3], e23.y, As);
        ffma2(ud[3], x23.y, Bp); ffma2(ud[3], y23.y, Bs);
        ffma2(us[3], d23.y, Cp); ffma2(us[3], e23.y, Cs);
    }
    #pragma unroll
    for (int j=0;j<4;++j){
        g_oud[((long)(bg*4+j)*64 + m)*CKD + o] = up2(ud[j]);
        g_ous[((long)(bg*4+j)*64 + m)*CKD + o] = up2(us[j]);
    }
}

// ---------------- folded inverse DFT: tile (8 tp x 2 ck)/thread, parity split ----------------
// block 256: tck = t&63 (ck pair), parity = (t>>6)&1, sub = t>>7 (tp subtile).
__global__ void __launch_bounds__(256) k_idft(long uoff, int n, int l, int stride, float invn){
    __shared__ ulonglong2 tab[64*16];
    __shared__ ull stash[16*128];
    int tck = threadIdx.x & 63;
    int parity = (threadIdx.x >> 6) & 1;
    int sub = threadIdx.x >> 7;
    int b  = blockIdx.y;
    int n2 = n >> 1;
    if (n2 == 0){
        if (threadIdx.x < 64){
            float4 yd = *(const float4*)((const float*)(g_oud + (long)b*64*CKD) + 4*tck);
            float4 ys = *(const float4*)((const float*)(g_ous + (long)b*64*CKD) + 4*tck);
            *(float2*)(g_ud + uoff + (long)b*CKD + 2*tck) = make_float2(yd.x, yd.z);
            *(float2*)(g_us + uoff + (long)b*CKD + 2*tck) = make_float2(ys.x, ys.z);
        }
        return;
    }
    int tb = blockIdx.x * 16;
    for (int q = threadIdx.x; q < l*16; q += 256){
        int m = q >> 4, tp = q & 15;
        int t = tb + tp;
        float2 e = make_float2(0.f, 0.f);
        float sc = 0.f;
        if (t < n2){
            e = g_tw[(m*t*stride) & 4095];
            sc = ((m==0) || (2*m==n)) ? invn : 2.f*invn;
        }
        tab[q] = make_ulonglong2(pk2(sc*e.x, sc*e.x), pk2(sc*e.y, sc*e.y));
    }
    __syncthreads();
    const float4* pod4 = (const float4*)(g_oud + (long)b*64*CKD) + tck;
    const float4* pos4 = (const float4*)(g_ous + (long)b*64*CKD) + tck;
    ull acc[16];
    #pragma unroll
    for (int i=0;i<16;++i) acc[i]=0ull;
    int mcount = (l - parity + 1) >> 1;
    if (mcount > 0){
        float4 yd = pod4[(long)parity*64];
        float4 ys = pos4[(long)parity*64];
        for (int k=0; k<mcount; ++k){
            int m = parity + 2*k;
            float4 ydn = make_float4(0,0,0,0), ysn = make_float4(0,0,0,0);
            if (k+1 < mcount){
                ydn = pod4[(long)(m+2)*64];
                ysn = pos4[(long)(m+2)*64];
            }
            ull re0 = pk2(yd.x, ys.x), im0 = pk2(yd.y, ys.y);
            ull re1 = pk2(yd.z, ys.z), im1 = pk2(yd.w, ys.w);
            const ulonglong2* row = &tab[m*16 + sub*8];
            #pragma unroll
            for (int tp=0; tp<8; ++tp){
                ulonglong2 t2 = row[tp];
                ffma2(acc[tp*2],   re0, t2.x);
                ffma2(acc[tp*2],   im0, t2.y);
                ffma2(acc[tp*2+1], re1, t2.x);
                ffma2(acc[tp*2+1], im1, t2.y);
            }
            yd = ydn; ys = ysn;
        }
    }
    if (parity == 0){
        #pragma unroll
        for (int i=0;i<16;++i) stash[i*128 + sub*64 + tck] = acc[i];
    }
    __syncthreads();
    if (parity == 1){
        float* pud = g_ud + uoff + (long)b*n*CKD + 2*tck;
        float* pus = g_us + uoff + (long)b*n*CKD + 2*tck;
        #pragma unroll
        for (int tp=0; tp<8; ++tp){
            int t = tb + sub*8 + tp;
            if (t < n2){
                float2 E0 = up2(stash[(tp*2)*128   + sub*64 + tck]);
                float2 E1 = up2(stash[(tp*2+1)*128 + sub*64 + tck]);
                float2 O0 = up2(acc[tp*2]), O1 = up2(acc[tp*2+1]);
                *(float2*)(pud + (long)t*CKD)      = make_float2(E0.x+O0.x, E1.x+O1.x);
                *(float2*)(pus + (long)t*CKD)      = make_float2(E0.y+O0.y, E1.y+O1.y);
                *(float2*)(pud + (long)(t+n2)*CKD) = make_float2(E0.x-O0.x, E1.x-O1.x);
                *(float2*)(pus + (long)(t+n2)*CKD) = make_float2(E0.y-O0.y, E1.y-O1.y);
            }
        }
    }
}

// ---------------- LayerNorm + exact GELU ----------------
__global__ void k_lngelu(const float* __restrict__ w, const float* __restrict__ bia, long off){
    int b = blockIdx.x, t = threadIdx.x;
    __shared__ float rs[8];
    float v = g_xs[off + (long)b*CKD + t];
    float s1 = v, s2 = v*v;
    #pragma unroll
    for (int o=16; o; o>>=1){
        s1 += __shfl_xor_sync(0xffffffffu, s1, o);
        s2 += __shfl_xor_sync(0xffffffffu, s2, o);
    }
    if ((t & 31) == 0){ rs[t>>5] = s1; rs[4+(t>>5)] = s2; }
    __syncthreads();
    float m1 = (rs[0]+rs[1]+rs[2]+rs[3]) * (1.0f/128.0f);
    float m2 = (rs[4]+rs[5]+rs[6]+rs[7]) * (1.0f/128.0f);
    float var = m2 - m1*m1;
    float xn = (v - m1) * rsqrtf(var + 1e-5f) * w[t] + bia[t];
    float ge = 0.5f * xn * (1.0f + erff(xn * 0.70710678118654752f));
    g_xs[off + (long)b*CKD + t] = ge;
}

// ---------------- host ----------------
extern "C" void kernel_launch(void* const* d_in, const int* in_sizes, int n_in,
                              void* d_out, int out_size) {
    const float* x   = (const float*)d_in[0];
    const float* Awr = (const float*)d_in[1];
    const float* Awi = (const float*)d_in[2];
    const float* Bwr = (const float*)d_in[3];
    const float* Bwi = (const float*)d_in[4];
    const float* Cwr = (const float*)d_in[5];
    const float* Cwi = (const float*)d_in[6];
    const float* lnw = (const float*)d_in[7];
    const float* lnb = (const float*)d_in[8];
    const float* ecs = (const float*)d_in[9];
    const float* ecd = (const float*)d_in[10];
    const float* rce = (const float*)d_in[11];
    const float* rco = (const float*)d_in[12];
    float* out = (float*)d_out;

    static const int NH[13]  = {4096,2048,1024,512,256,128,64,32,16,8,4,2,1};
    static const int LM[13]  = {64,64,64,64,64,64,33,17,9,5,3,2,1};
    static const int SSP[13] = {16,16,8,4,2,1,1,1,1,1,1,1,1};
    long OFF[13];
    OFF[0] = 0;
    for (int l=1; l<13; ++l) OFF[l] = OFF[l-1] + (long)16*NH[l-1]*128;

    k_base<<<16, 256>>>();
    long wthr = (long)3*64*128*128;
    k_wtrans<<<(unsigned)((wthr+255)/256), 256>>>(Awr, Awi, Bwr, Bwi, Cwr, Cwi);

    for (int l=0; l<13; ++l){
        int nh = NH[l], lm = LM[l], ssp = SSP[l], stride = 4096 / nh;
        long nthr = (long)16*nh*16;
        unsigned blk = (unsigned)((nthr + 255) / 256);
        k_decompose<<<blk, 256>>>(l==0 ? x : (const float*)0, l ? OFF[l-1] : 0,
                                  OFF[l], ecs, ecd, nh);
        dim3 gf((lm+15)/16, ssp, 32);
        k_fdft<<<gf, 128>>>(OFF[l], ssp>1 ? 1 : 0, nh, lm, stride);
        if (ssp > 1){
            unsigned rb = (unsigned)(((long)16*lm*128 + 255)/256);
            k_ftred<<<dim3(rb, 2), 256>>>(lm, ssp);
        }
        k_mix<<<dim3(lm, 4), 128>>>(lm);
        int n2 = nh >> 1;
        int gx = (n2 == 0) ? 1 : (n2 + 15)/16;
        k_idft<<<dim3(gx, 16), 256>>>(OFF[l], nh, lm, stride, 1.0f/(float)nh);
    }

    k_lngelu<<<16, 128>>>(lnw, lnb, OFF[12]);

    for (int l=12; l>=0; --l){
        int nh = NH[l];
        long nthr = (long)16*nh*16;
        unsigned blk = (unsigned)((nthr + 255) / 256);
        k_recon<<<blk, 256>>>(OFF[l], OFF[l],
                              l ? (float*)0 : out, l ? OFF[l-1] : 0,
                              rce, rco, nh);
    }
}